// round 15
// baseline (speedup 1.0000x reference)
#include <cuda_runtime.h>

#define NB 256
#define NP 512
#define NH 16
#define NK 8
#define HTP 520           // transposed pitch (floats); 2080B rows, 16B-aligned
#define YP  20            // y-row pitch (floats), bank-spread for gather
#define RP  17            // pool-reduce row pitch

typedef unsigned long long ull;

__device__ __forceinline__ float elu1(float x) {
    return x > 0.f ? x : (__expf(x) - 1.f);
}

// ---- f32x2 packed helpers (fma/add/mul only — no packed min/max on sm_103a) ----
__device__ __forceinline__ ull fma2(ull a, ull b, ull c) {
    ull d; asm("fma.rn.f32x2 %0, %1, %2, %3;" : "=l"(d) : "l"(a), "l"(b), "l"(c)); return d;
}
__device__ __forceinline__ ull add2(ull a, ull b) {
    ull d; asm("add.rn.f32x2 %0, %1, %2;" : "=l"(d) : "l"(a), "l"(b)); return d;
}
__device__ __forceinline__ ull pack2(float lo, float hi) {
    ull d; asm("mov.b64 %0, {%1, %2};" : "=l"(d) : "f"(lo), "f"(hi)); return d;
}
__device__ __forceinline__ float2 unpack2(ull v) {
    float lo, hi; asm("mov.b64 {%0, %1}, %2;" : "=f"(lo), "=f"(hi) : "l"(v));
    return make_float2(lo, hi);
}

// key = bits(d2 + 1.0), low 9 bits = j. d2+1 >= ~1 (positive normal) -> uint order ok.
__device__ __forceinline__ unsigned packkey(float d2p1, int j) {
    return (__float_as_uint(d2p1) & 0xFFFFFE00u) | (unsigned)j;
}

#define CE(x, y) { unsigned _lo = umin(x, y); y = umax(x, y); x = _lo; }

// Optimal 19-CE sorting network for 8 keys (ascending).
__device__ __forceinline__ void sort8(unsigned (&k)[8]) {
    CE(k[0],k[1]); CE(k[2],k[3]); CE(k[4],k[5]); CE(k[6],k[7]);
    CE(k[0],k[2]); CE(k[1],k[3]); CE(k[4],k[6]); CE(k[5],k[7]);
    CE(k[1],k[2]); CE(k[5],k[6]); CE(k[0],k[4]); CE(k[3],k[7]);
    CE(k[1],k[5]); CE(k[2],k[6]);
    CE(k[1],k[4]); CE(k[3],k[6]);
    CE(k[2],k[4]); CE(k[3],k[5]);
    CE(k[3],k[4]);
}

// nd (asc) <- 8 smallest of nd ∪ k (k asc 8). min-pair (bitonic) + clean-up.
__device__ __forceinline__ void mergeTop8(unsigned (&nd)[NK], const unsigned (&k)[8]) {
    unsigned L[8];
#pragma unroll
    for (int i = 0; i < 8; i++) L[i] = umin(nd[i], k[7-i]);
    CE(L[0],L[4]); CE(L[1],L[5]); CE(L[2],L[6]); CE(L[3],L[7]);
    CE(L[0],L[2]); CE(L[1],L[3]); CE(L[4],L[6]); CE(L[5],L[7]);
    CE(L[0],L[1]); CE(L[2],L[3]); CE(L[4],L[5]); CE(L[6],L[7]);
#pragma unroll
    for (int i = 0; i < 8; i++) nd[i] = L[i];
}

// --------------------------------------------------------------- conv ------
// One edgeconv pass, 2 i-rows per thread (256 threads). region holds hT
// (pitch HTP), sqsh the norms. d2+1 is accumulated directly: low chain starts
// at (sq_i + 1 + sq_j) and sums (-2 h_d) * v_d; no separate finalize fma.
__device__ __forceinline__ void conv_pass(
    float* region, float* sqsh,
    const float* w2t, const float* wdt, const float* bcs,
    int tid, float (&op)[2][NH])
{
    ull hiA2n[NH], hiB2n[NH];   // pack2(-2h, -2h)
#pragma unroll
    for (int d = 0; d < NH; d++) {
        float a = -2.f * region[d*HTP + tid];
        float c = -2.f * region[d*HTP + tid + 256];
        hiA2n[d] = pack2(a, a);
        hiB2n[d] = pack2(c, c);
    }
    ull sqA2p1 = pack2(sqsh[tid] + 1.f,       sqsh[tid] + 1.f);
    ull sqB2p1 = pack2(sqsh[tid + 256] + 1.f, sqsh[tid + 256] + 1.f);

    unsigned ndA[NK], ndB[NK];
#pragma unroll
    for (int k = 0; k < NK; k++) { ndA[k] = 0xFFFFFFFFu; ndB[k] = 0xFFFFFFFFu; }

#pragma unroll 2
    for (int j = 0; j < NP; j += 8) {
        unsigned kkA[8], kkB[8];
#pragma unroll
        for (int s = 0; s < 2; s++) {
            int jj = j + s*4;
            ulonglong2 sj = *reinterpret_cast<const ulonglong2*>(&sqsh[jj]);
            // low chains init with (sq_i + 1 + sq_j); high chains init 0
            ull a0 = add2(sqA2p1, sj.x), a1 = add2(sqA2p1, sj.y);
            ull b0 = add2(sqB2p1, sj.x), b1 = add2(sqB2p1, sj.y);
            ull a0H = 0ull, a1H = 0ull, b0H = 0ull, b1H = 0ull;
#pragma unroll
            for (int d = 0; d < 8; d++) {
                ulonglong2 v = *reinterpret_cast<const ulonglong2*>(&region[d*HTP + jj]);
                a0 = fma2(hiA2n[d], v.x, a0);
                a1 = fma2(hiA2n[d], v.y, a1);
                b0 = fma2(hiB2n[d], v.x, b0);
                b1 = fma2(hiB2n[d], v.y, b1);
            }
#pragma unroll
            for (int d = 8; d < 16; d++) {
                ulonglong2 v = *reinterpret_cast<const ulonglong2*>(&region[d*HTP + jj]);
                a0H = fma2(hiA2n[d], v.x, a0H);
                a1H = fma2(hiA2n[d], v.y, a1H);
                b0H = fma2(hiB2n[d], v.x, b0H);
                b1H = fma2(hiB2n[d], v.y, b1H);
            }
            {
                ull d01 = add2(a0, a0H);     // = d2 + 1 for (jj, jj+1)
                ull d23 = add2(a1, a1H);
                float2 p01 = unpack2(d01), p23 = unpack2(d23);
                kkA[s*4+0] = packkey(p01.x, jj);   kkA[s*4+1] = packkey(p01.y, jj+1);
                kkA[s*4+2] = packkey(p23.x, jj+2); kkA[s*4+3] = packkey(p23.y, jj+3);
            }
            {
                ull d01 = add2(b0, b0H);
                ull d23 = add2(b1, b1H);
                float2 p01 = unpack2(d01), p23 = unpack2(d23);
                kkB[s*4+0] = packkey(p01.x, jj);   kkB[s*4+1] = packkey(p01.y, jj+1);
                kkB[s*4+2] = packkey(p23.x, jj+2); kkB[s*4+3] = packkey(p23.y, jj+3);
            }
        }
        sort8(kkA); mergeTop8(ndA, kkA);
        sort8(kkB); mergeTop8(ndB, kkB);
    }

    // ---- base + y for both rows (hT still live), then swap region to y ----
    float base[2][NH], yrow[2][NH];
#pragma unroll
    for (int t2 = 0; t2 < 2; t2++) {
        int r = tid + t2*256;
        float f[NH];
#pragma unroll
        for (int d = 0; d < NH; d++) f[d] = region[d*HTP + r];
#pragma unroll
        for (int c = 0; c < NH; c++) {
            float av = bcs[c];
            float y = 0.f;
#pragma unroll
            for (int d = 0; d < NH; d++) {
                av = fmaf(f[d], wdt[c*NH+d], av);
                y  = fmaf(f[d], w2t[c*NH+d], y);
            }
            base[t2][c] = av;
            yrow[t2][c] = y;
        }
    }
    __syncthreads();   // all hT reads complete
#pragma unroll
    for (int t2 = 0; t2 < 2; t2++) {
        int r = tid + t2*256;
#pragma unroll
        for (int c = 0; c < NH; c++) region[r*YP + c] = yrow[t2][c];
    }
    __syncthreads();

    // ---- gather: m = base_i + y_j ; max over 8 edges; single elu ----
#pragma unroll
    for (int t2 = 0; t2 < 2; t2++) {
        const unsigned* nd = (t2 == 0) ? ndA : ndB;
        float acc[NH];
#pragma unroll
        for (int c = 0; c < NH; c++) acc[c] = -3.4e38f;
#pragma unroll
        for (int e = 0; e < NK; e++) {
            int j = nd[e] & 511u;
            const float4* yp = reinterpret_cast<const float4*>(&region[j*YP]);
            float4 v0 = yp[0], v1 = yp[1], v2 = yp[2], v3 = yp[3];
            float yv[NH];
            yv[0]=v0.x; yv[1]=v0.y; yv[2]=v0.z; yv[3]=v0.w;
            yv[4]=v1.x; yv[5]=v1.y; yv[6]=v1.z; yv[7]=v1.w;
            yv[8]=v2.x; yv[9]=v2.y; yv[10]=v2.z; yv[11]=v2.w;
            yv[12]=v3.x; yv[13]=v3.y; yv[14]=v3.z; yv[15]=v3.w;
#pragma unroll
            for (int c = 0; c < NH; c++) acc[c] = fmaxf(acc[c], base[t2][c] + yv[c]);
        }
#pragma unroll
        for (int c = 0; c < NH; c++) op[t2][c] = elu1(acc[c]);  // elu(max)==max(elu)
    }
}

// ------------------------------------------------------------- fused -------
// One CTA = one graph: embed -> conv0 -> conv1 -> pool -> head, one kernel.
__global__ void __launch_bounds__(256, 2) k_fused(
    const float* __restrict__ x,
    const float* __restrict__ We1, const float* __restrict__ be1,
    const float* __restrict__ We2, const float* __restrict__ be2,
    const float* __restrict__ Wc,  const float* __restrict__ bc,
    const float* __restrict__ Wo1, const float* __restrict__ bo1,
    const float* __restrict__ Wo2, const float* __restrict__ bo2,
    const float* __restrict__ Wo3, const float* __restrict__ bo3,
    float* __restrict__ out, int out_size)
{
    __shared__ __align__(16) float region[NP*YP];    // hT -> y -> hT -> y -> pool
    __shared__ __align__(16) float sqsh[NP];
    __shared__ float w2t[NH*NH];   // [c][d] = Wc[(16+d)*16+c]
    __shared__ float wdt[NH*NH];   // [c][d] = Wc[d*16+c] - w2
    __shared__ float bcs[NH];

    int tid = threadIdx.x;
    int b   = blockIdx.x;

    // ---- prologue: fused embed -> hT + norms (8+8 split chain) ----
#pragma unroll
    for (int t2 = 0; t2 < 2; t2++) {
        int r = tid + t2*256;
        float4 xv = reinterpret_cast<const float4*>(x)[b*NP + r];
        float t[NH], f[NH];
#pragma unroll
        for (int c = 0; c < NH; c++) {
            float a = __ldg(&be1[c]);
            a = fmaf(xv.x, __ldg(&We1[0*NH+c]), a);
            a = fmaf(xv.y, __ldg(&We1[1*NH+c]), a);
            a = fmaf(xv.z, __ldg(&We1[2*NH+c]), a);
            a = fmaf(xv.w, __ldg(&We1[3*NH+c]), a);
            t[c] = elu1(a);
        }
#pragma unroll
        for (int c = 0; c < NH; c++) {
            float a = __ldg(&be2[c]);
#pragma unroll
            for (int d = 0; d < NH; d++) a = fmaf(t[d], __ldg(&We2[d*NH+c]), a);
            f[c] = elu1(a);
        }
#pragma unroll
        for (int d = 0; d < NH; d++) region[d*HTP + r] = f[d];
        float sL = 0.f, sH = 0.f;
#pragma unroll
        for (int d = 0; d < 8; d++)  sL = fmaf(f[d], f[d], sL);
#pragma unroll
        for (int d = 8; d < 16; d++) sH = fmaf(f[d], f[d], sH);
        sqsh[r] = sL + sH;
    }
    {   // W_c prep: transposed + xi/xj regroup
        int c = tid >> 4, d = tid & 15;
        float w1 = Wc[d*NH + c];
        float w2 = Wc[(NH+d)*NH + c];
        w2t[c*NH+d] = w2;
        wdt[c*NH+d] = w1 - w2;
    }
    if (tid < NH) bcs[tid] = bc[tid];
    __syncthreads();

    float op[2][NH];
    conv_pass(region, sqsh, w2t, wdt, bcs, tid, op);   // conv0

    // ---- re-seed region with f1 (transposed) + norms ----
    __syncthreads();   // conv0 gather reads of region(y) complete
#pragma unroll
    for (int t2 = 0; t2 < 2; t2++) {
        int r = tid + t2*256;
#pragma unroll
        for (int d = 0; d < NH; d++) region[d*HTP + r] = op[t2][d];
        float sL = 0.f, sH = 0.f;
#pragma unroll
        for (int d = 0; d < 8; d++)  sL = fmaf(op[t2][d], op[t2][d], sL);
#pragma unroll
        for (int d = 8; d < 16; d++) sH = fmaf(op[t2][d], op[t2][d], sH);
        sqsh[r] = sL + sH;
    }
    __syncthreads();

    conv_pass(region, sqsh, w2t, wdt, bcs, tid, op);   // conv1

    // ---- fused mean-pool + head ----
    __syncthreads();   // conv1 gather reads of region done
#pragma unroll
    for (int c = 0; c < NH; c++) region[tid*RP + c] = op[0][c] + op[1][c];
    __syncthreads();
    {
        int c = tid & 15, part = tid >> 4;
        float s = 0.f;
#pragma unroll
        for (int k = 0; k < 16; k++) s += region[(part + k*16)*RP + c];
        sqsh[tid] = s;
    }
    __syncthreads();
    if (tid < NH) {
        float t = 0.f;
#pragma unroll
        for (int k = 0; k < 16; k++) t += sqsh[k*16 + tid];
        sqsh[tid] = t * (1.0f/NP);       // pooled mean, channels 0..15
    }
    __syncthreads();
    if (tid == 0) {
        float p[NH];
#pragma unroll
        for (int c = 0; c < NH; c++) p[c] = sqsh[c];
        float t1[8];
#pragma unroll
        for (int cc = 0; cc < 8; cc++) {
            float a = __ldg(&bo1[cc]);
#pragma unroll
            for (int d = 0; d < 16; d++) a = fmaf(p[d], __ldg(&Wo1[d*8+cc]), a);
            t1[cc] = elu1(a);
        }
        float t2[4];
#pragma unroll
        for (int cc = 0; cc < 4; cc++) {
            float a = __ldg(&bo2[cc]);
#pragma unroll
            for (int d = 0; d < 8; d++) a = fmaf(t1[d], __ldg(&Wo2[d*4+cc]), a);
            t2[cc] = elu1(a);
        }
        float o = __ldg(&bo3[0]);
#pragma unroll
        for (int d = 0; d < 4; d++) o = fmaf(t2[d], __ldg(&Wo3[d]), o);
        out[b] = o;
        if (out_size >= 2*NB) out[NB + b] = (float)b;   // pooled_batch = arange(B)
    }
}

// --------------------------------------------------------------- launch ----
extern "C" void kernel_launch(void* const* d_in, const int* in_sizes, int n_in,
                              void* d_out, int out_size)
{
    int wb = n_in - 12;
    const float* x   = (const float*)d_in[0];
    const float* We1 = (const float*)d_in[wb+0];
    const float* be1 = (const float*)d_in[wb+1];
    const float* We2 = (const float*)d_in[wb+2];
    const float* be2 = (const float*)d_in[wb+3];
    const float* Wc  = (const float*)d_in[wb+4];
    const float* bcp = (const float*)d_in[wb+5];
    const float* Wo1 = (const float*)d_in[wb+6];
    const float* bo1 = (const float*)d_in[wb+7];
    const float* Wo2 = (const float*)d_in[wb+8];
    const float* bo2 = (const float*)d_in[wb+9];
    const float* Wo3 = (const float*)d_in[wb+10];
    const float* bo3 = (const float*)d_in[wb+11];

    k_fused<<<NB, 256>>>(x, We1, be1, We2, be2, Wc, bcp,
                         Wo1, bo1, Wo2, bo2, Wo3, bo3,
                         (float*)d_out, out_size);
}

// round 16
// speedup vs baseline: 1.0344x; 1.0344x over previous
#include <cuda_runtime.h>

#define NB 256
#define NP 512
#define NH 16
#define NK 8
#define HTP 520           // transposed pitch (floats); 2080B rows, 16B-aligned
#define YP  20            // y-row pitch (floats), bank-spread for gather
#define RP  17            // pool-reduce row pitch

typedef unsigned long long ull;

__device__ __forceinline__ float elu1(float x) {
    return x > 0.f ? x : (__expf(x) - 1.f);
}

// ---- f32x2 packed helpers (fma/add/mul only — no packed min/max on sm_103a) ----
__device__ __forceinline__ ull fma2(ull a, ull b, ull c) {
    ull d; asm("fma.rn.f32x2 %0, %1, %2, %3;" : "=l"(d) : "l"(a), "l"(b), "l"(c)); return d;
}
__device__ __forceinline__ ull add2(ull a, ull b) {
    ull d; asm("add.rn.f32x2 %0, %1, %2;" : "=l"(d) : "l"(a), "l"(b)); return d;
}
__device__ __forceinline__ ull pack2(float lo, float hi) {
    ull d; asm("mov.b64 %0, {%1, %2};" : "=l"(d) : "f"(lo), "f"(hi)); return d;
}
__device__ __forceinline__ float2 unpack2(ull v) {
    float lo, hi; asm("mov.b64 {%0, %1}, %2;" : "=f"(lo), "=f"(hi) : "l"(v));
    return make_float2(lo, hi);
}

// key = bits(d2 + 1.0), low 9 bits = j. d2+1 >= ~1 (positive normal) -> uint order ok.
__device__ __forceinline__ unsigned packkey(float d2p1, int j) {
    return (__float_as_uint(d2p1) & 0xFFFFFE00u) | (unsigned)j;
}

#define CE(x, y) { unsigned _lo = umin(x, y); y = umax(x, y); x = _lo; }

// Optimal 19-CE sorting network for 8 keys (ascending).
__device__ __forceinline__ void sort8(unsigned (&k)[8]) {
    CE(k[0],k[1]); CE(k[2],k[3]); CE(k[4],k[5]); CE(k[6],k[7]);
    CE(k[0],k[2]); CE(k[1],k[3]); CE(k[4],k[6]); CE(k[5],k[7]);
    CE(k[1],k[2]); CE(k[5],k[6]); CE(k[0],k[4]); CE(k[3],k[7]);
    CE(k[1],k[5]); CE(k[2],k[6]);
    CE(k[1],k[4]); CE(k[3],k[6]);
    CE(k[2],k[4]); CE(k[3],k[5]);
    CE(k[3],k[4]);
}

// nd (asc) <- 8 smallest of nd ∪ k (k asc 8). min-pair (bitonic) + clean-up.
__device__ __forceinline__ void mergeTop8(unsigned (&nd)[NK], const unsigned (&k)[8]) {
    unsigned L[8];
#pragma unroll
    for (int i = 0; i < 8; i++) L[i] = umin(nd[i], k[7-i]);
    CE(L[0],L[4]); CE(L[1],L[5]); CE(L[2],L[6]); CE(L[3],L[7]);
    CE(L[0],L[2]); CE(L[1],L[3]); CE(L[4],L[6]); CE(L[5],L[7]);
    CE(L[0],L[1]); CE(L[2],L[3]); CE(L[4],L[5]); CE(L[6],L[7]);
#pragma unroll
    for (int i = 0; i < 8; i++) nd[i] = L[i];
}

// --------------------------------------------------------------- conv ------
// One edgeconv pass, 2 i-rows per thread (256 threads). region holds hT
// (pitch HTP), sqsh the norms. Dot chains are split 2-way (d 0-7 / d 8-15)
// to halve the dependence depth; sq uses the SAME split -> exact self-0.
// sqsh[jj] is consumed only in the finalize fma so its LDS latency hides
// behind the chains (folding it into the init regressed — R15 post-mortem).
__device__ __forceinline__ void conv_pass(
    float* region, float* sqsh,
    const float* w2t, const float* wdt, const float* bcs,
    int tid, float (&op)[2][NH])
{
    ull hiA[NH], hiB[NH];
#pragma unroll
    for (int d = 0; d < NH; d++) {
        float a = region[d*HTP + tid];
        float c = region[d*HTP + tid + 256];
        hiA[d] = pack2(a, a);
        hiB[d] = pack2(c, c);
    }
    ull sqA2p1 = pack2(sqsh[tid] + 1.f,       sqsh[tid] + 1.f);
    ull sqB2p1 = pack2(sqsh[tid + 256] + 1.f, sqsh[tid + 256] + 1.f);
    ull neg2   = pack2(-2.f, -2.f);

    unsigned ndA[NK], ndB[NK];
#pragma unroll
    for (int k = 0; k < NK; k++) { ndA[k] = 0xFFFFFFFFu; ndB[k] = 0xFFFFFFFFu; }

#pragma unroll 2
    for (int j = 0; j < NP; j += 8) {
        unsigned kkA[8], kkB[8];
#pragma unroll
        for (int s = 0; s < 2; s++) {
            int jj = j + s*4;
            // 2-way split accumulators: halves the serial FMA2 chain depth
            ull a0L = 0ull, a1L = 0ull, b0L = 0ull, b1L = 0ull;
            ull a0H = 0ull, a1H = 0ull, b0H = 0ull, b1H = 0ull;
#pragma unroll
            for (int d = 0; d < 8; d++) {
                ulonglong2 v = *reinterpret_cast<const ulonglong2*>(&region[d*HTP + jj]);
                a0L = fma2(hiA[d], v.x, a0L);
                a1L = fma2(hiA[d], v.y, a1L);
                b0L = fma2(hiB[d], v.x, b0L);
                b1L = fma2(hiB[d], v.y, b1L);
            }
#pragma unroll
            for (int d = 8; d < 16; d++) {
                ulonglong2 v = *reinterpret_cast<const ulonglong2*>(&region[d*HTP + jj]);
                a0H = fma2(hiA[d], v.x, a0H);
                a1H = fma2(hiA[d], v.y, a1H);
                b0H = fma2(hiB[d], v.x, b0H);
                b1H = fma2(hiB[d], v.y, b1H);
            }
            ull a0 = add2(a0L, a0H), a1 = add2(a1L, a1H);
            ull b0 = add2(b0L, b0H), b1 = add2(b1L, b1H);
            ulonglong2 sj = *reinterpret_cast<const ulonglong2*>(&sqsh[jj]);
            {
                ull d01 = fma2(neg2, a0, add2(sqA2p1, sj.x));
                ull d23 = fma2(neg2, a1, add2(sqA2p1, sj.y));
                float2 p01 = unpack2(d01), p23 = unpack2(d23);
                kkA[s*4+0] = packkey(p01.x, jj);   kkA[s*4+1] = packkey(p01.y, jj+1);
                kkA[s*4+2] = packkey(p23.x, jj+2); kkA[s*4+3] = packkey(p23.y, jj+3);
            }
            {
                ull d01 = fma2(neg2, b0, add2(sqB2p1, sj.x));
                ull d23 = fma2(neg2, b1, add2(sqB2p1, sj.y));
                float2 p01 = unpack2(d01), p23 = unpack2(d23);
                kkB[s*4+0] = packkey(p01.x, jj);   kkB[s*4+1] = packkey(p01.y, jj+1);
                kkB[s*4+2] = packkey(p23.x, jj+2); kkB[s*4+3] = packkey(p23.y, jj+3);
            }
        }
        sort8(kkA); mergeTop8(ndA, kkA);
        sort8(kkB); mergeTop8(ndB, kkB);
    }

    // ---- base + y for both rows (hT still live), then swap region to y ----
    float base[2][NH], yrow[2][NH];
#pragma unroll
    for (int t2 = 0; t2 < 2; t2++) {
        int r = tid + t2*256;
        float f[NH];
#pragma unroll
        for (int d = 0; d < NH; d++) f[d] = region[d*HTP + r];
#pragma unroll
        for (int c = 0; c < NH; c++) {
            float av = bcs[c];
            float y = 0.f;
#pragma unroll
            for (int d = 0; d < NH; d++) {
                av = fmaf(f[d], wdt[c*NH+d], av);
                y  = fmaf(f[d], w2t[c*NH+d], y);
            }
            base[t2][c] = av;
            yrow[t2][c] = y;
        }
    }
    __syncthreads();   // all hT reads complete
#pragma unroll
    for (int t2 = 0; t2 < 2; t2++) {
        int r = tid + t2*256;
#pragma unroll
        for (int c = 0; c < NH; c++) region[r*YP + c] = yrow[t2][c];
    }
    __syncthreads();

    // ---- gather: m = base_i + y_j ; max over 8 edges; single elu ----
#pragma unroll
    for (int t2 = 0; t2 < 2; t2++) {
        const unsigned* nd = (t2 == 0) ? ndA : ndB;
        float acc[NH];
#pragma unroll
        for (int c = 0; c < NH; c++) acc[c] = -3.4e38f;
#pragma unroll
        for (int e = 0; e < NK; e++) {
            int j = nd[e] & 511u;
            const float4* yp = reinterpret_cast<const float4*>(&region[j*YP]);
            float4 v0 = yp[0], v1 = yp[1], v2 = yp[2], v3 = yp[3];
            float yv[NH];
            yv[0]=v0.x; yv[1]=v0.y; yv[2]=v0.z; yv[3]=v0.w;
            yv[4]=v1.x; yv[5]=v1.y; yv[6]=v1.z; yv[7]=v1.w;
            yv[8]=v2.x; yv[9]=v2.y; yv[10]=v2.z; yv[11]=v2.w;
            yv[12]=v3.x; yv[13]=v3.y; yv[14]=v3.z; yv[15]=v3.w;
#pragma unroll
            for (int c = 0; c < NH; c++) acc[c] = fmaxf(acc[c], base[t2][c] + yv[c]);
        }
#pragma unroll
        for (int c = 0; c < NH; c++) op[t2][c] = elu1(acc[c]);  // elu(max)==max(elu)
    }
}

// ------------------------------------------------------------- fused -------
// One CTA = one graph: embed -> conv0 -> conv1 -> pool -> head, one kernel.
__global__ void __launch_bounds__(256, 2) k_fused(
    const float* __restrict__ x,
    const float* __restrict__ We1, const float* __restrict__ be1,
    const float* __restrict__ We2, const float* __restrict__ be2,
    const float* __restrict__ Wc,  const float* __restrict__ bc,
    const float* __restrict__ Wo1, const float* __restrict__ bo1,
    const float* __restrict__ Wo2, const float* __restrict__ bo2,
    const float* __restrict__ Wo3, const float* __restrict__ bo3,
    float* __restrict__ out, int out_size)
{
    __shared__ __align__(16) float region[NP*YP];    // hT -> y -> hT -> y -> pool
    __shared__ __align__(16) float sqsh[NP];
    __shared__ float w2t[NH*NH];   // [c][d] = Wc[(16+d)*16+c]
    __shared__ float wdt[NH*NH];   // [c][d] = Wc[d*16+c] - w2
    __shared__ float bcs[NH];

    int tid = threadIdx.x;
    int b   = blockIdx.x;

    // ---- prologue: fused embed -> hT + norms (8+8 split chain == dot split) ----
#pragma unroll
    for (int t2 = 0; t2 < 2; t2++) {
        int r = tid + t2*256;
        float4 xv = reinterpret_cast<const float4*>(x)[b*NP + r];
        float t[NH], f[NH];
#pragma unroll
        for (int c = 0; c < NH; c++) {
            float a = __ldg(&be1[c]);
            a = fmaf(xv.x, __ldg(&We1[0*NH+c]), a);
            a = fmaf(xv.y, __ldg(&We1[1*NH+c]), a);
            a = fmaf(xv.z, __ldg(&We1[2*NH+c]), a);
            a = fmaf(xv.w, __ldg(&We1[3*NH+c]), a);
            t[c] = elu1(a);
        }
#pragma unroll
        for (int c = 0; c < NH; c++) {
            float a = __ldg(&be2[c]);
#pragma unroll
            for (int d = 0; d < NH; d++) a = fmaf(t[d], __ldg(&We2[d*NH+c]), a);
            f[c] = elu1(a);
        }
#pragma unroll
        for (int d = 0; d < NH; d++) region[d*HTP + r] = f[d];
        float sL = 0.f, sH = 0.f;   // same split as the packed dot -> exact self-0
#pragma unroll
        for (int d = 0; d < 8; d++)  sL = fmaf(f[d], f[d], sL);
#pragma unroll
        for (int d = 8; d < 16; d++) sH = fmaf(f[d], f[d], sH);
        sqsh[r] = sL + sH;
    }
    {   // W_c prep: transposed + xi/xj regroup
        int c = tid >> 4, d = tid & 15;
        float w1 = Wc[d*NH + c];
        float w2 = Wc[(NH+d)*NH + c];
        w2t[c*NH+d] = w2;
        wdt[c*NH+d] = w1 - w2;
    }
    if (tid < NH) bcs[tid] = bc[tid];
    __syncthreads();

    float op[2][NH];
    conv_pass(region, sqsh, w2t, wdt, bcs, tid, op);   // conv0

    // ---- re-seed region with f1 (transposed) + norms ----
    __syncthreads();   // conv0 gather reads of region(y) complete
#pragma unroll
    for (int t2 = 0; t2 < 2; t2++) {
        int r = tid + t2*256;
#pragma unroll
        for (int d = 0; d < NH; d++) region[d*HTP + r] = op[t2][d];
        float sL = 0.f, sH = 0.f;
#pragma unroll
        for (int d = 0; d < 8; d++)  sL = fmaf(op[t2][d], op[t2][d], sL);
#pragma unroll
        for (int d = 8; d < 16; d++) sH = fmaf(op[t2][d], op[t2][d], sH);
        sqsh[r] = sL + sH;
    }
    __syncthreads();

    conv_pass(region, sqsh, w2t, wdt, bcs, tid, op);   // conv1

    // ---- fused mean-pool + head ----
    __syncthreads();   // conv1 gather reads of region done
#pragma unroll
    for (int c = 0; c < NH; c++) region[tid*RP + c] = op[0][c] + op[1][c];
    __syncthreads();
    {
        int c = tid & 15, part = tid >> 4;
        float s = 0.f;
#pragma unroll
        for (int k = 0; k < 16; k++) s += region[(part + k*16)*RP + c];
        sqsh[tid] = s;
    }
    __syncthreads();
    if (tid < NH) {
        float t = 0.f;
#pragma unroll
        for (int k = 0; k < 16; k++) t += sqsh[k*16 + tid];
        sqsh[tid] = t * (1.0f/NP);       // pooled mean, channels 0..15
    }
    __syncthreads();
    if (tid == 0) {
        float p[NH];
#pragma unroll
        for (int c = 0; c < NH; c++) p[c] = sqsh[c];
        float t1[8];
#pragma unroll
        for (int cc = 0; cc < 8; cc++) {
            float a = __ldg(&bo1[cc]);
#pragma unroll
            for (int d = 0; d < 16; d++) a = fmaf(p[d], __ldg(&Wo1[d*8+cc]), a);
            t1[cc] = elu1(a);
        }
        float t2[4];
#pragma unroll
        for (int cc = 0; cc < 4; cc++) {
            float a = __ldg(&bo2[cc]);
#pragma unroll
            for (int d = 0; d < 8; d++) a = fmaf(t1[d], __ldg(&Wo2[d*4+cc]), a);
            t2[cc] = elu1(a);
        }
        float o = __ldg(&bo3[0]);
#pragma unroll
        for (int d = 0; d < 4; d++) o = fmaf(t2[d], __ldg(&Wo3[d]), o);
        out[b] = o;
        if (out_size >= 2*NB) out[NB + b] = (float)b;   // pooled_batch = arange(B)
    }
}

// --------------------------------------------------------------- launch ----
extern "C" void kernel_launch(void* const* d_in, const int* in_sizes, int n_in,
                              void* d_out, int out_size)
{
    int wb = n_in - 12;
    const float* x   = (const float*)d_in[0];
    const float* We1 = (const float*)d_in[wb+0];
    const float* be1 = (const float*)d_in[wb+1];
    const float* We2 = (const float*)d_in[wb+2];
    const float* be2 = (const float*)d_in[wb+3];
    const float* Wc  = (const float*)d_in[wb+4];
    const float* bcp = (const float*)d_in[wb+5];
    const float* Wo1 = (const float*)d_in[wb+6];
    const float* bo1 = (const float*)d_in[wb+7];
    const float* Wo2 = (const float*)d_in[wb+8];
    const float* bo2 = (const float*)d_in[wb+9];
    const float* Wo3 = (const float*)d_in[wb+10];
    const float* bo3 = (const float*)d_in[wb+11];

    k_fused<<<NB, 256>>>(x, We1, be1, We2, be2, Wc, bcp,
                         Wo1, bo1, Wo2, bo2, Wo3, bo3,
                         (float*)d_out, out_size);
}